// round 17
// baseline (speedup 1.0000x reference)
#include <cuda_runtime.h>
#include <cstdint>
#include <math.h>

#define NT     16
#define S_LEN  4096
#define B_SZ   512
#define HALF   (S_LEN / 2)                 // 2048 iterations
#define CHUNK  8
#define NBLK   (B_SZ / 4)                  // 128 blocks, 4 rows each

typedef unsigned long long u64;

// Per-row partial results + completion counter (device globals: legal scratch).
__device__ float g_fwd[B_SZ];
__device__ float g_gold[B_SZ];
__device__ unsigned g_done = 0;

// ---- packed fp32x2 math ----
__device__ __forceinline__ u64 mul2(u64 a, u64 b) {
    u64 d; asm("mul.rn.f32x2 %0, %1, %2;" : "=l"(d) : "l"(a), "l"(b)); return d;
}
__device__ __forceinline__ u64 fma2(u64 a, u64 b, u64 c) {
    u64 d; asm("fma.rn.f32x2 %0, %1, %2, %3;" : "=l"(d) : "l"(a), "l"(b), "l"(c)); return d;
}
__device__ __forceinline__ u64 add2(u64 a, u64 b) {
    u64 d; asm("add.rn.f32x2 %0, %1, %2;" : "=l"(d) : "l"(a), "l"(b)); return d;
}
__device__ __forceinline__ u64 pack2(float lo, float hi) {
    u64 d; asm("mov.b64 %0, {%1, %2};" : "=l"(d) : "f"(lo), "f"(hi)); return d;
}
__device__ __forceinline__ void unpack2(u64 v, float& lo, float& hi) {
    asm("mov.b64 {%0, %1}, %2;" : "=f"(lo), "=f"(hi) : "l"(v));
}

__device__ __forceinline__ float dot16(const u64* v, const u64* c) {
    u64 p0 = mul2(v[0], c[0]);
    u64 p1 = mul2(v[1], c[1]);
    u64 p2 = mul2(v[2], c[2]);
    u64 p3 = mul2(v[3], c[3]);
    p0 = fma2(v[4], c[4], p0);
    p1 = fma2(v[5], c[5], p1);
    p2 = fma2(v[6], c[6], p2);
    p3 = fma2(v[7], c[7], p3);
    const u64 q0 = add2(p0, p1);
    const u64 q1 = add2(p2, p3);
    const u64 qq = add2(q0, q1);
    float lo, hi;
    unpack2(qq, lo, hi);
    return lo + hi;
}

// Butterfly all-gather within 4-lane stream (2 rounds: xor 1, 2).
// Lane holds quad (4h..4h+3) as sA=(4h,4h+1), sB=(4h+2,4h+3).
// Arrival order: v[i] = pair(g = h^(i>>1), half = i&1).
__device__ __forceinline__ void bfly4(u64 sA, u64 sB, u64* v) {
    v[0] = sA;
    v[1] = sB;
    v[2] = __shfl_xor_sync(0xffffffffu, sA, 1);
    v[3] = __shfl_xor_sync(0xffffffffu, sB, 1);
    v[4] = __shfl_xor_sync(0xffffffffu, v[0], 2);
    v[5] = __shfl_xor_sync(0xffffffffu, v[1], 2);
    v[6] = __shfl_xor_sync(0xffffffffu, v[2], 2);
    v[7] = __shfl_xor_sync(0xffffffffu, v[3], 2);
}

// Detect element strides (bytes) of tags/mask buffers (JAX dtype ambiguity).
__device__ __forceinline__ int detect_mask_stride(const unsigned char* mb) {
    return (mb[1] | mb[2] | mb[3]) ? 1 : 4;
}
__device__ __forceinline__ int detect_tag_stride(const void* tp) {
    const int* w = (const int*)tp;
    int nz = 0;
#pragma unroll
    for (int k = 0; k < 32; ++k) nz |= w[1 + 2 * k];
    return nz ? 4 : 8;
}

// One block = 96 threads = 3 warps, 4 batch rows.
//   warp 0: bidirectional scan, 8 streams of 4 lanes:
//           q = lane>>2: r = q>>1 (row 0..3), dir = q&1; lane owns tags 4h..4h+3.
//           fwd: alpha_t = w_t.(E^T alpha_{t-1});  bwd (delta): d_t = (E d_{t+1}).w_t
//   warps 1,2: gold path score, 2 rows each (verbatim proven code).
__global__ void __launch_bounds__(96, 1) crf_fused_kernel(
    const float* __restrict__ emissions,          // [B, S, NT] f32
    const void*  __restrict__ tags_raw,           // [B, S] i32 or i64
    const void*  __restrict__ mask_raw,           // [B, S] u8 or i32 (bool)
    const float* __restrict__ transitions,        // [NT, NT] f32
    const float* __restrict__ start_t,            // [NT] f32
    const float* __restrict__ end_t,              // [NT] f32
    float* __restrict__ out)
{
    const int warp = threadIdx.x >> 5;
    const int lane = threadIdx.x & 31;

    const unsigned char* mask_b = (const unsigned char*)mask_raw;
    const unsigned char* tags_b = (const unsigned char*)tags_raw;
    const int mstride = detect_mask_stride(mask_b);
    const int tstride = detect_tag_stride(tags_raw);

    __shared__ int s_last;

    if (warp == 0) {
        const int q   = lane >> 2;                // stream id (0..7)
        const int r   = q >> 1;                   // row within block (0..3)
        const int dir = q & 1;                    // 0 fwd, 1 bwd
        const int h   = lane & 3;                 // owns tags 4h..4h+3
        const int row = blockIdx.x * 4 + r;
        const int sbl = lane & 28;                // stream base lane (h = 0)

        // dot constants, butterfly arrival order.
        // output jo: tag j = 4h+jo.  v[i] covers tags (ta, tb) of (g, half).
        u64 C[4][8];
#pragma unroll
        for (int jo = 0; jo < 4; ++jo) {
            const int j = 4 * h + jo;
#pragma unroll
            for (int i = 0; i < 8; ++i) {
                const int g  = h ^ (i >> 1);
                const int ta = 4 * g + 2 * (i & 1);
                const int tb = ta + 1;
                const int a0 = dir ? (j * NT + ta) : (ta * NT + j);
                const int a1 = dir ? (j * NT + tb) : (tb * NT + j);
                C[jo][i] = pack2(__expf(transitions[a0]), __expf(transitions[a1]));
            }
        }

        const float4* erow4 =
            reinterpret_cast<const float4*>(emissions + (size_t)row * S_LEN * NT) + h;
        const unsigned char* mrowb = mask_b + (size_t)row * S_LEN * mstride;
        const float dirf = dir ? 1.0f : 0.0f;

        // prologue prefetch. iteration i: fwd e_i, m_i; bwd e_{S-1-i}, m_{S-i}.
        float4 ebuf[CHUNK];
        int    mbuf[CHUNK];
#pragma unroll
        for (int p = 0; p < CHUNK; ++p) {
            const int et = dir ? (S_LEN - 1 - p) : p;
            const int mt = dir ? ((p == 0) ? S_LEN - 1 : S_LEN - p) : p;
            ebuf[p] = erow4[(size_t)et * 4];
            mbuf[p] = mrowb[(size_t)mt * mstride];
        }
        mbuf[0] = 0;                              // iteration 0 = init step

        // steady-state prefetch pointers (pointer-bump only; always in-bounds)
        const int estep = dir ? -4 : 4;           // float4 units per t
        const int mstep = dir ? -mstride : mstride;
        const float4* epf = erow4 + (dir ? (size_t)(S_LEN - 1 - CHUNK) * 4
                                         : (size_t)CHUNK * 4);
        const unsigned char* mpf = mrowb + (dir ? (size_t)(S_LEN - CHUNK) * mstride
                                                : (size_t)CHUNK * mstride);

        // init: fwd alpha_0 = exp(start + e_0); bwd d_{S-1} = exp(end + e_{S-1})
        const float* bt = dir ? end_t : start_t;
        float s0 = __expf(bt[4 * h + 0] + ebuf[0].x);
        float s1 = __expf(bt[4 * h + 1] + ebuf[0].y);
        float s2 = __expf(bt[4 * h + 2] + ebuf[0].z);
        float s3 = __expf(bt[4 * h + 3] + ebuf[0].w);
        float4 ep = ebuf[0];
        int    ksum = 0;

        for (int tb = 0; tb < HALF; tb += CHUNK) {
#pragma unroll
            for (int u = 0; u < CHUNK; ++u) {
                const float4 e = ebuf[u];
                const int    m = mbuf[u];

                // off-chain emission weights (e loaded CHUNK iterations ago)
                const unsigned pb0 = __float_as_uint(__expf(e.x)) + 0x3f800000u;
                const unsigned pb1 = __float_as_uint(__expf(e.y)) + 0x3f800000u;
                const unsigned pb2 = __float_as_uint(__expf(e.z)) + 0x3f800000u;
                const unsigned pb3 = __float_as_uint(__expf(e.w)) + 0x3f800000u;
                // masked arm: fwd keep s (exp(0)); bwd s*exp(e_new - e_old)
                const float sR0 = s0 * __expf((e.x - ep.x) * dirf);
                const float sR1 = s1 * __expf((e.y - ep.y) * dirf);
                const float sR2 = s2 * __expf((e.z - ep.z) * dirf);
                const float sR3 = s3 * __expf((e.w - ep.w) * dirf);

                // pair-0 exponent broadcast (uniform scale across the stream)
                const unsigned ub =
                    __shfl_sync(0xffffffffu, __float_as_uint(s0), sbl);

                // register butterfly all-gather (2 rounds)
                u64 v[8];
                bfly4(pack2(s0, s1), pack2(s2, s3), v);

                // prefetch (always in-bounds within the row)
                ebuf[u] = *epf;  epf += estep;
                mbuf[u] = *mpf;  mpf += mstep;

                // exponent fold: P = w * 2^-k from stream state[0]
                const int kcur = (int)((ub >> 23) & 0xffu) - 127;
                const unsigned msk = ub & 0x7f800000u;
                const float P0 = __uint_as_float(pb0 - msk);
                const float P1 = __uint_as_float(pb1 - msk);
                const float P2 = __uint_as_float(pb2 - msk);
                const float P3 = __uint_as_float(pb3 - msk);

                // four independent packed trees (one per owned output tag)
                const float a0 = dot16(v, C[0]);
                const float a1 = dot16(v, C[1]);
                const float a2 = dot16(v, C[2]);
                const float a3 = dot16(v, C[3]);

                s0    = m ? (a0 * P0) : sR0;
                s1    = m ? (a1 * P1) : sR1;
                s2    = m ? (a2 * P2) : sR2;
                s3    = m ? (a3 * P3) : sR3;
                ksum += m * kcur;
                ep    = e;
            }
        }

        // ---------------- join (all 32 lanes participate in every shfl) --------
        u64 vf[8];
        bfly4(pack2(s0, s1), pack2(s2, s3), vf);
        const float y0 = dot16(vf, C[0]);          // fwd lanes: (E^T alpha_2047)_j
        const float y1 = dot16(vf, C[1]);
        const float y2 = dot16(vf, C[2]);
        const float y3 = dot16(vf, C[3]);

        // partner stream (other direction of same row) = lane ^ 4
        const u64 pA = __shfl_xor_sync(0xffffffffu, pack2(s0, s1), 4);
        const u64 pB = __shfl_xor_sync(0xffffffffu, pack2(s2, s3), 4);
        const int kB = __shfl_xor_sync(0xffffffffu, ksum, 4);
        float d0, d1, d2, d3;
        unpack2(pA, d0, d1);
        unpack2(pB, d2, d3);

        const int mju = mrowb[(size_t)HALF * mstride];
        const float4 e2k = erow4[(size_t)HALF * 4];
        // m=1: logZ = sum_j y_j * delta_{2048,j}
        // m=0: beta_2047 = beta_2048 -> sum_j alpha_j * delta_j / w_{2048,j}
        const float t0 = mju ? (y0 * d0) : (s0 * d0 * __expf(-e2k.x));
        const float t1 = mju ? (y1 * d1) : (s1 * d1 * __expf(-e2k.y));
        const float t2 = mju ? (y2 * d2) : (s2 * d2 * __expf(-e2k.z));
        const float t3 = mju ? (y3 * d3) : (s3 * d3 * __expf(-e2k.w));

        float z = (t0 + t1) + (t2 + t3);
        z += __shfl_xor_sync(0xffffffffu, z, 1, 4);
        z += __shfl_xor_sync(0xffffffffu, z, 2, 4);
        if (dir == 0 && h == 0)
            g_fwd[row] = logf(z) + (float)(ksum + kB) * 0.6931471805599453f;
    } else {
        // ---------------- gold path score (concurrent, verbatim R14) ----------
        const int j   = lane & 15;
        const int row = blockIdx.x * 4 + (warp - 1) * 2 + (lane >> 4);
        const unsigned char* trow = tags_b + (size_t)row * S_LEN * tstride;
        const unsigned char* mrow = mask_b + (size_t)row * S_LEN * mstride;
        const float*         erow = emissions + (size_t)row * S_LEN * NT;

        float acc = 0.0f;
        int   cnt = 0;
        for (int t = j; t < S_LEN; t += 16) {
            const int tg = trow[(size_t)t * tstride];
            const int mm = mrow[(size_t)t * mstride];
            cnt += mm ? 1 : 0;
            if (t == 0) {
                acc += start_t[tg] + erow[tg];
            } else if (mm) {
                const int tpv = trow[(size_t)(t - 1) * tstride];
                acc += transitions[tpv * NT + tg] + erow[(size_t)t * NT + tg];
            }
        }
#pragma unroll
        for (int off = 8; off >= 1; off >>= 1) {
            acc += __shfl_xor_sync(0xffffffffu, acc, off, 16);
            cnt += __shfl_xor_sync(0xffffffffu, cnt, off, 16);
        }
        if (j == 0) {
            int last = cnt - 1;
            if (last < 0) last = 0;
            const int lt = trow[(size_t)last * tstride];
            g_gold[row] = acc + end_t[lt];
        }
    }

    // ---------------- last-block global reduction ----------------
    __syncthreads();
    if (threadIdx.x == 0) {
        __threadfence();
        const unsigned old = atomicAdd(&g_done, 1u);
        s_last = (old == NBLK - 1u) ? 1 : 0;
    }
    __syncthreads();
    if (s_last) {
        __threadfence();
        float a = 0.0f;
        for (int i = threadIdx.x; i < B_SZ; i += 96)
            a += g_fwd[i] - g_gold[i];
#pragma unroll
        for (int off = 16; off >= 1; off >>= 1)
            a += __shfl_xor_sync(0xffffffffu, a, off);
        __shared__ float wsum[3];
        if ((threadIdx.x & 31) == 0) wsum[threadIdx.x >> 5] = a;
        __syncthreads();
        if (threadIdx.x == 0) {
            out[0] = (wsum[0] + wsum[1] + wsum[2]) * (1.0f / (float)B_SZ);
            g_done = 0;                      // reset for next graph replay
        }
    }
}

extern "C" void kernel_launch(void* const* d_in, const int* in_sizes, int n_in,
                              void* d_out, int out_size)
{
    (void)in_sizes; (void)n_in; (void)out_size;
    const float* emissions   = (const float*)d_in[0];
    const void*  tags        = d_in[1];
    const void*  mask        = d_in[2];
    const float* transitions = (const float*)d_in[3];
    const float* start_t     = (const float*)d_in[4];
    const float* end_t       = (const float*)d_in[5];

    crf_fused_kernel<<<NBLK, 96>>>(emissions, tags, mask, transitions,
                                   start_t, end_t, (float*)d_out);
}